// round 3
// baseline (speedup 1.0000x reference)
#include <cuda_runtime.h>
#include <cstdint>

// Problem constants
#define BQ   8
#define HQ   16
#define NQ   8192
#define HD   64
#define NJ   20
#define TILE 64          // query positions per block
#define HALO 128         // largest offset served from smem
#define HROWS (TILE + HALO)   // 192 rows in halo

__device__ __constant__ int g_unused;  // (nothing)

static __device__ __forceinline__ unsigned long long pk2(float lo, float hi) {
    unsigned long long r;
    asm("mov.b64 %0, {%1,%2};" : "=l"(r) : "f"(lo), "f"(hi));
    return r;
}
static __device__ __forceinline__ unsigned long long f2add(unsigned long long a, unsigned long long b) {
    unsigned long long r;
    asm("add.rn.f32x2 %0, %1, %2;" : "=l"(r) : "l"(a), "l"(b));
    return r;
}
static __device__ __forceinline__ unsigned long long f2fma(unsigned long long a, unsigned long long b, unsigned long long c) {
    unsigned long long r;
    asm("fma.rn.f32x2 %0, %1, %2, %3;" : "=l"(r) : "l"(a), "l"(b), "l"(c));
    return r;
}
static __device__ __forceinline__ float f2hadd(unsigned long long a) {
    float lo, hi;
    asm("mov.b64 {%0,%1}, %2;" : "=f"(lo), "=f"(hi) : "l"(a));
    return lo + hi;
}

// offsets (compile-time folded in unrolled loops)
__device__ __forceinline__ constexpr int offs(int j) {
    constexpr int O[NJ] = {1,2,3,4,5,6,7,8,9,11,13,15,16,23,32,64,128,256,512,1024};
    return O[j];
}

// smem floats: k halo + v halo + scale_embed + pos_bias
#define SK_FLOATS  (HROWS * HD)      // 12288
#define SSE_FLOATS (NJ * HD)         // 1280
#define SMEM_FLOATS (2 * SK_FLOATS + SSE_FLOATS + 32)
#define SMEM_BYTES  (SMEM_FLOATS * 4)

__global__ void __launch_bounds__(512, 2)
dsqg_attn_kernel(const float* __restrict__ q,
                 const float* __restrict__ k,
                 const float* __restrict__ v,
                 const float* __restrict__ pb,   // [NJ, HQ]
                 const float* __restrict__ se,   // [NJ, HD]
                 float* __restrict__ out)
{
    extern __shared__ float sm[];
    float* sk  = sm;                       // [HROWS][HD]
    float* sv  = sm + SK_FLOATS;           // [HROWS][HD]
    float* sse = sm + 2 * SK_FLOATS;       // [NJ][HD]
    float* spb = sse + SSE_FLOATS;         // [NJ]

    const int bh   = blockIdx.y;           // 0..127 = b*HQ + h
    const int h    = bh & (HQ - 1);
    const int n0   = blockIdx.x * TILE;
    const int base = bh * (NQ * HD);       // fits in int (max 6.7e7)
    const int tid  = threadIdx.x;

    // ---- cooperative fills ----
    {
        const int total4 = SK_FLOATS / 4;  // 3072 float4 per halo
        const int e0 = (n0 - HALO) * HD;   // slice-relative element of halo start (can be <0 only for blockIdx.x==0)
        #pragma unroll 2
        for (int i = tid; i < total4; i += 512) {
            int ge = e0 + i * 4;
            float4 kv = make_float4(0.f, 0.f, 0.f, 0.f);
            float4 vv = kv;
            if (ge >= 0) {
                kv = *(const float4*)(k + base + ge);
                vv = *(const float4*)(v + base + ge);
            }
            ((float4*)sk)[i] = kv;
            ((float4*)sv)[i] = vv;
        }
        for (int i = tid; i < SSE_FLOATS / 4; i += 512)
            ((float4*)sse)[i] = ((const float4*)se)[i];
        if (tid < NJ) spb[tid] = pb[tid * HQ + h];
    }
    __syncthreads();

    const int g  = tid >> 4;       // group 0..31, one position at a time (2 total)
    const int l  = tid & 15;       // lane within group
    const int c0 = l * 4;          // channel base
    const float NEG_INF = __int_as_float(0xff800000);

    #pragma unroll
    for (int p = 0; p < 2; ++p) {
        const int nl = g * 2 + p;       // 0..63 local position
        const int n  = n0 + nl;         // global position

        // load q (two f32x2 packs)
        const unsigned long long* q2p = (const unsigned long long*)(q + base + n * HD + c0);
        const unsigned long long q01 = q2p[0];
        const unsigned long long q23 = q2p[1];

        float s[NJ];

        // ---- pass 1: scores ----
        #pragma unroll
        for (int j = 0; j < NJ; ++j) {
            const int d = offs(j);
            unsigned long long k01, k23;
            if (d <= HALO) {
                const unsigned long long* kp =
                    (const unsigned long long*)(sk + (nl + HALO - d) * HD + c0);
                k01 = kp[0]; k23 = kp[1];
            } else {
                if (n >= d) {
                    const unsigned long long* kp =
                        (const unsigned long long*)(k + base + (n - d) * HD + c0);
                    k01 = kp[0]; k23 = kp[1];
                } else {
                    k01 = 0ull; k23 = 0ull;
                }
            }
            const unsigned long long* sep = (const unsigned long long*)(sse + j * HD + c0);
            // t = k + se ; partial = dot(q, t)
            unsigned long long t0 = f2add(k01, sep[0]);
            unsigned long long t1 = f2add(k23, sep[1]);
            unsigned long long acc = f2fma(q01, t0, f2fma(q23, t1, 0ull));
            float partial = f2hadd(acc);
            // 16-lane reduction (uniform across warp: full-mask shuffles)
            partial += __shfl_xor_sync(0xffffffffu, partial, 1);
            partial += __shfl_xor_sync(0xffffffffu, partial, 2);
            partial += __shfl_xor_sync(0xffffffffu, partial, 4);
            partial += __shfl_xor_sync(0xffffffffu, partial, 8);
            s[j] = (n >= d) ? fmaf(partial, 0.125f, spb[j]) : NEG_INF;
        }

        float4* outp = (float4*)(out + base + n * HD + c0);

        if (n == 0) {   // no valid offsets: reference yields zeros
            *outp = make_float4(0.f, 0.f, 0.f, 0.f);
            continue;
        }

        // ---- softmax over 20 (redundant per lane; m finite since d=1 valid for n>=1) ----
        float m = s[0];
        #pragma unroll
        for (int j = 1; j < NJ; ++j) m = fmaxf(m, s[j]);
        float denom = 0.f;
        #pragma unroll
        for (int j = 0; j < NJ; ++j) {
            s[j] = __expf(s[j] - m);   // exp(-inf)=0 for masked
            denom += s[j];
        }
        const float inv = __frcp_rn(denom);

        // ---- pass 2: weighted V accumulation ----
        unsigned long long a01 = 0ull, a23 = 0ull;
        #pragma unroll
        for (int j = 0; j < NJ; ++j) {
            const int d = offs(j);
            unsigned long long v01, v23;
            if (d <= HALO) {
                const unsigned long long* vp =
                    (const unsigned long long*)(sv + (nl + HALO - d) * HD + c0);
                v01 = vp[0]; v23 = vp[1];
            } else {
                if (n >= d) {
                    const unsigned long long* vp =
                        (const unsigned long long*)(v + base + (n - d) * HD + c0);
                    v01 = vp[0]; v23 = vp[1];
                } else {
                    v01 = 0ull; v23 = 0ull;
                }
            }
            const float w = s[j] * inv;
            const unsigned long long w2 = pk2(w, w);
            a01 = f2fma(w2, v01, a01);
            a23 = f2fma(w2, v23, a23);
        }
        // store
        unsigned long long* outq = (unsigned long long*)outp;
        outq[0] = a01;
        outq[1] = a23;
    }
}

extern "C" void kernel_launch(void* const* d_in, const int* in_sizes, int n_in,
                              void* d_out, int out_size)
{
    const float* q  = (const float*)d_in[0];
    const float* k  = (const float*)d_in[1];
    const float* v  = (const float*)d_in[2];
    const float* pb = (const float*)d_in[3];
    const float* se = (const float*)d_in[4];
    float* out = (float*)d_out;

    cudaFuncSetAttribute(dsqg_attn_kernel,
                         cudaFuncAttributeMaxDynamicSharedMemorySize, SMEM_BYTES);

    dim3 grid(NQ / TILE, BQ * HQ);
    dsqg_attn_kernel<<<grid, 512, SMEM_BYTES>>>(q, k, v, pb, se, out);
}

// round 4
// speedup vs baseline: 1.7424x; 1.7424x over previous
#include <cuda_runtime.h>
#include <cstdint>

// Problem constants
#define BQ   8
#define HQ   16
#define NQ   8192
#define HD   64
#define NJ   20
#define TILE 64          // query positions per block
#define HALO 128         // largest offset served from smem
#define HROWS (TILE + HALO)   // 192 rows in halo

static __device__ __forceinline__ unsigned long long pk2(float lo, float hi) {
    unsigned long long r;
    asm("mov.b64 %0, {%1,%2};" : "=l"(r) : "f"(lo), "f"(hi));
    return r;
}
static __device__ __forceinline__ unsigned long long f2add(unsigned long long a, unsigned long long b) {
    unsigned long long r;
    asm("add.rn.f32x2 %0, %1, %2;" : "=l"(r) : "l"(a), "l"(b));
    return r;
}
static __device__ __forceinline__ unsigned long long f2fma(unsigned long long a, unsigned long long b, unsigned long long c) {
    unsigned long long r;
    asm("fma.rn.f32x2 %0, %1, %2, %3;" : "=l"(r) : "l"(a), "l"(b), "l"(c));
    return r;
}
static __device__ __forceinline__ float f2hadd(unsigned long long a) {
    float lo, hi;
    asm("mov.b64 {%0,%1}, %2;" : "=f"(lo), "=f"(hi) : "l"(a));
    return lo + hi;
}

// offsets (compile-time folded in unrolled loops)
__device__ __forceinline__ constexpr int offs(int j) {
    constexpr int O[NJ] = {1,2,3,4,5,6,7,8,9,11,13,15,16,23,32,64,128,256,512,1024};
    return O[j];
}

// smem floats: k halo + v halo + scale_embed + pos_bias
#define SK_FLOATS  (HROWS * HD)      // 12288
#define SSE_FLOATS (NJ * HD)         // 1280
#define SMEM_FLOATS (2 * SK_FLOATS + SSE_FLOATS + 32)
#define SMEM_BYTES  (SMEM_FLOATS * 4)

__global__ void __launch_bounds__(512, 2)
dsqg_attn_kernel(const float* __restrict__ q,
                 const float* __restrict__ k,
                 const float* __restrict__ v,
                 const float* __restrict__ pb,   // [NJ, HQ]
                 const float* __restrict__ se,   // [NJ, HD]
                 float* __restrict__ out)
{
    extern __shared__ float sm[];
    float* sk  = sm;                       // [HROWS][HD]
    float* sv  = sm + SK_FLOATS;           // [HROWS][HD]
    float* sse = sm + 2 * SK_FLOATS;       // [NJ][HD]
    float* spb = sse + SSE_FLOATS;         // [NJ]

    const int bh   = blockIdx.y;           // 0..127 = b*HQ + h
    const int h    = bh & (HQ - 1);
    const int n0   = blockIdx.x * TILE;
    const int base = bh * (NQ * HD);
    const int tid  = threadIdx.x;

    // ---- cooperative fills (coalesced float4) ----
    {
        const int total4 = SK_FLOATS / 4;  // 3072 float4 per halo
        const int e0 = (n0 - HALO) * HD;
        #pragma unroll 2
        for (int i = tid; i < total4; i += 512) {
            int ge = e0 + i * 4;
            float4 kv = make_float4(0.f, 0.f, 0.f, 0.f);
            float4 vv = kv;
            if (ge >= 0) {
                kv = *(const float4*)(k + base + ge);
                vv = *(const float4*)(v + base + ge);
            }
            ((float4*)sk)[i] = kv;
            ((float4*)sv)[i] = vv;
        }
        for (int i = tid; i < SSE_FLOATS / 4; i += 512)
            ((float4*)sse)[i] = ((const float4*)se)[i];
        if (tid < NJ) spb[tid] = pb[tid * HQ + h];
    }
    __syncthreads();

    // 8-lane groups: group g owns position n0+g; lane l owns channels
    // [4l..4l+3] and [32+4l..32+4l+3]  -> conflict-free 16B smem accesses.
    const int g  = tid >> 3;       // 0..63
    const int l  = tid & 7;        // 0..7
    const int c0 = l * 4;
    const int c1 = 32 + l * 4;
    const int nl = g;
    const int n  = n0 + g;
    const float NEG_INF = __int_as_float(0xff800000);

    // q: two 16B loads, coalesced across the warp (4 consecutive rows)
    const float* qr = q + base + n * HD;
    const ulonglong2 Q0 = *(const ulonglong2*)(qr + c0);
    const ulonglong2 Q1 = *(const ulonglong2*)(qr + c1);

    float s[NJ];

    // ---- pass 1: scores ----
    #pragma unroll
    for (int j = 0; j < NJ; ++j) {
        const int d = offs(j);
        ulonglong2 K0, K1;
        if (d <= HALO) {                   // compile-time branch
            const float* kr = sk + (nl + HALO - d) * HD;
            K0 = *(const ulonglong2*)(kr + c0);
            K1 = *(const ulonglong2*)(kr + c1);
        } else {
            if (n >= d) {
                const float* kr = k + base + (n - d) * HD;
                K0 = *(const ulonglong2*)(kr + c0);
                K1 = *(const ulonglong2*)(kr + c1);
            } else {
                K0.x = K0.y = K1.x = K1.y = 0ull;
            }
        }
        const float* ser = sse + j * HD;
        const ulonglong2 S0 = *(const ulonglong2*)(ser + c0);
        const ulonglong2 S1 = *(const ulonglong2*)(ser + c1);

        unsigned long long t =
            f2fma(Q0.x, f2add(K0.x, S0.x),
            f2fma(Q0.y, f2add(K0.y, S0.y),
            f2fma(Q1.x, f2add(K1.x, S1.x),
            f2fma(Q1.y, f2add(K1.y, S1.y), 0ull))));
        float p = f2hadd(t);
        // 8-lane butterfly (uniform across warp)
        p += __shfl_xor_sync(0xffffffffu, p, 1);
        p += __shfl_xor_sync(0xffffffffu, p, 2);
        p += __shfl_xor_sync(0xffffffffu, p, 4);
        s[j] = (n >= d) ? fmaf(p, 0.125f, spb[j]) : NEG_INF;
    }

    float* outr = out + base + n * HD;

    if (n == 0) {   // no valid offsets: reference yields zeros
        *(float4*)(outr + c0) = make_float4(0.f, 0.f, 0.f, 0.f);
        *(float4*)(outr + c1) = make_float4(0.f, 0.f, 0.f, 0.f);
    } else {
        // ---- softmax over 20 (redundant per lane, cheap) ----
        float m = s[0];
        #pragma unroll
        for (int j = 1; j < NJ; ++j) m = fmaxf(m, s[j]);
        float denom = 0.f;
        #pragma unroll
        for (int j = 0; j < NJ; ++j) {
            s[j] = __expf(s[j] - m);   // exp(-inf)=0 for masked
            denom += s[j];
        }
        const float inv = __frcp_rn(denom);

        // ---- pass 2: weighted V accumulation ----
        unsigned long long a00 = 0ull, a01 = 0ull, a10 = 0ull, a11 = 0ull;
        #pragma unroll
        for (int j = 0; j < NJ; ++j) {
            const int d = offs(j);
            ulonglong2 V0, V1;
            if (d <= HALO) {
                const float* vr = sv + (nl + HALO - d) * HD;
                V0 = *(const ulonglong2*)(vr + c0);
                V1 = *(const ulonglong2*)(vr + c1);
            } else {
                if (n >= d) {
                    const float* vr = v + base + (n - d) * HD;
                    V0 = *(const ulonglong2*)(vr + c0);
                    V1 = *(const ulonglong2*)(vr + c1);
                } else {
                    V0.x = V0.y = V1.x = V1.y = 0ull;
                }
            }
            const float w = s[j] * inv;
            const unsigned long long w2 = pk2(w, w);
            a00 = f2fma(w2, V0.x, a00);
            a01 = f2fma(w2, V0.y, a01);
            a10 = f2fma(w2, V1.x, a10);
            a11 = f2fma(w2, V1.y, a11);
        }
        ulonglong2 R0; R0.x = a00; R0.y = a01;
        ulonglong2 R1; R1.x = a10; R1.y = a11;
        *(ulonglong2*)(outr + c0) = R0;
        *(ulonglong2*)(outr + c1) = R1;
    }
}

extern "C" void kernel_launch(void* const* d_in, const int* in_sizes, int n_in,
                              void* d_out, int out_size)
{
    const float* q  = (const float*)d_in[0];
    const float* k  = (const float*)d_in[1];
    const float* v  = (const float*)d_in[2];
    const float* pb = (const float*)d_in[3];
    const float* se = (const float*)d_in[4];
    float* out = (float*)d_out;

    cudaFuncSetAttribute(dsqg_attn_kernel,
                         cudaFuncAttributeMaxDynamicSharedMemorySize, SMEM_BYTES);

    dim3 grid(NQ / TILE, BQ * HQ);
    dsqg_attn_kernel<<<grid, 512, SMEM_BYTES>>>(q, k, v, pb, se, out);
}